// round 1
// baseline (speedup 1.0000x reference)
#include <cuda_runtime.h>
#include <float.h>
#include <math.h>

#define BATCH 2
#define NPTS 8192
#define KNN 16
#define TILE 4096            // 3 * 4096 * 4B = 49152B = exactly the 48KB static smem limit
#define THREADS 128
#define NBLOCKS (2 * BATCH * NPTS / THREADS)   // 2 dirs * 2 batches * 8192 / 128 = 256

__device__ float g_partials[NBLOCKS];

__global__ void __launch_bounds__(THREADS)
chamfer_knn_kernel(const float* __restrict__ src,
                   const float* __restrict__ tgt,
                   const float* __restrict__ flow) {
    __shared__ float sx[TILE], sy[TILE], sz[TILE];

    const int tid = threadIdx.x;
    const int blocks_per_set = NPTS / THREADS;        // 64
    const int set = blockIdx.x / blocks_per_set;      // 0..3 : (batch, direction)
    const int b   = set >> 1;
    const int dir = set & 1;                          // 0: pred->target, 1: target->pred
    const int qi  = (blockIdx.x % blocks_per_set) * THREADS + tid;

    const float* __restrict__ srcb = src  + (size_t)b * NPTS * 3;
    const float* __restrict__ tgtb = tgt  + (size_t)b * NPTS * 3;
    const float* __restrict__ flob = flow + (size_t)b * NPTS * 3;

    // query point
    float qx, qy, qz;
    if (dir == 0) {
        qx = srcb[qi * 3 + 0] + flob[qi * 3 + 0];
        qy = srcb[qi * 3 + 1] + flob[qi * 3 + 1];
        qz = srcb[qi * 3 + 2] + flob[qi * 3 + 2];
    } else {
        qx = tgtb[qi * 3 + 0];
        qy = tgtb[qi * 3 + 1];
        qz = tgtb[qi * 3 + 2];
    }

    // top-16 smallest squared distances, kept sorted DESCENDING (best[0] = worst)
    float best[KNN];
#pragma unroll
    for (int i = 0; i < KNN; i++) best[i] = FLT_MAX;

    for (int t0 = 0; t0 < NPTS; t0 += TILE) {
        // stage ref tile into shared (SoA)
        for (int p = tid; p < TILE; p += THREADS) {
            const int g = t0 + p;
            float x, y, z;
            if (dir == 0) {
                x = tgtb[g * 3 + 0];
                y = tgtb[g * 3 + 1];
                z = tgtb[g * 3 + 2];
            } else {
                x = srcb[g * 3 + 0] + flob[g * 3 + 0];
                y = srcb[g * 3 + 1] + flob[g * 3 + 1];
                z = srcb[g * 3 + 2] + flob[g * 3 + 2];
            }
            sx[p] = x; sy[p] = y; sz[p] = z;
        }
        __syncthreads();

#pragma unroll 8
        for (int j = 0; j < TILE; j++) {
            const float dx = qx - sx[j];
            const float dy = qy - sy[j];
            const float dz = qz - sz[j];
            const float d2 = fmaf(dx, dx, fmaf(dy, dy, dz * dz));
            if (d2 < best[0]) {
                // replace worst, one bubble pass restores descending order
                best[0] = d2;
#pragma unroll
                for (int i = 0; i < KNN - 1; i++) {
                    const float a = best[i], c = best[i + 1];
                    best[i]     = fmaxf(a, c);
                    best[i + 1] = fminf(a, c);
                }
            }
        }
        __syncthreads();   // also guarantees sx reuse below is safe
    }

    // per-query sum of the 16 euclidean distances
    float s = 0.f;
#pragma unroll
    for (int i = 0; i < KNN; i++) s += sqrtf(best[i]);

    // deterministic block reduction (warp shuffle + fixed-order combine in sx)
#pragma unroll
    for (int o = 16; o > 0; o >>= 1) s += __shfl_down_sync(0xffffffffu, s, o);
    if ((tid & 31) == 0) sx[tid >> 5] = s;
    __syncthreads();
    if (tid == 0) {
        float tot = 0.f;
#pragma unroll
        for (int w = 0; w < THREADS / 32; w++) tot += sx[w];
        g_partials[blockIdx.x] = tot;
    }
}

__global__ void __launch_bounds__(NBLOCKS)
finalize_kernel(float* __restrict__ out) {
    __shared__ float sh[NBLOCKS];
    const int tid = threadIdx.x;
    sh[tid] = g_partials[tid];
    __syncthreads();
#pragma unroll
    for (int s = NBLOCKS / 2; s > 0; s >>= 1) {
        if (tid < s) sh[tid] += sh[tid + s];
        __syncthreads();
    }
    if (tid == 0) {
        // total_sum_of_sqrt / (K * B * N)  ==  (dist1 + dist2).mean()
        out[0] = sh[0] * (1.0f / (float)(KNN * BATCH * NPTS));
    }
}

extern "C" void kernel_launch(void* const* d_in, const int* in_sizes, int n_in,
                              void* d_out, int out_size) {
    const float* src  = (const float*)d_in[0];   // pc_source [B, N, 3]
    const float* tgt  = (const float*)d_in[1];   // pc_target [B, M, 3]
    const float* flow = (const float*)d_in[2];   // pred_flow [B, N, 3]
    float* out = (float*)d_out;

    chamfer_knn_kernel<<<NBLOCKS, THREADS>>>(src, tgt, flow);
    finalize_kernel<<<1, NBLOCKS>>>(out);
}

// round 2
// speedup vs baseline: 1.0369x; 1.0369x over previous
#include <cuda_runtime.h>
#include <float.h>
#include <math.h>

#define BATCH 2
#define NPTS 8192
#define KNN 16
#define TILE 2048            // 2048 * 16B (float4) = 32 KB static smem
#define THREADS 128
#define NBLOCKS (2 * BATCH * NPTS / THREADS)   // 256

__device__ float g_partials[NBLOCKS];

__global__ void __launch_bounds__(THREADS)
chamfer_knn_kernel(const float* __restrict__ src,
                   const float* __restrict__ tgt,
                   const float* __restrict__ flow) {
    __shared__ float4 spts[TILE];

    const int tid = threadIdx.x;
    const int blocks_per_set = NPTS / THREADS;        // 64
    const int set = blockIdx.x / blocks_per_set;      // 0..3 : (batch, direction)
    const int b   = set >> 1;
    const int dir = set & 1;                          // 0: pred->target, 1: target->pred
    const int qi  = (blockIdx.x % blocks_per_set) * THREADS + tid;

    const float* __restrict__ srcb = src  + (size_t)b * NPTS * 3;
    const float* __restrict__ tgtb = tgt  + (size_t)b * NPTS * 3;
    const float* __restrict__ flob = flow + (size_t)b * NPTS * 3;

    // query point
    float qx, qy, qz;
    if (dir == 0) {
        qx = srcb[qi * 3 + 0] + flob[qi * 3 + 0];
        qy = srcb[qi * 3 + 1] + flob[qi * 3 + 1];
        qz = srcb[qi * 3 + 2] + flob[qi * 3 + 2];
    } else {
        qx = tgtb[qi * 3 + 0];
        qy = tgtb[qi * 3 + 1];
        qz = tgtb[qi * 3 + 2];
    }

    // top-16 smallest squared distances, sorted DESCENDING (best[0] = worst of the 16)
    float best[KNN];
#pragma unroll
    for (int i = 0; i < KNN; i++) best[i] = FLT_MAX;

    for (int t0 = 0; t0 < NPTS; t0 += TILE) {
        // stage ref tile into shared as float4 (x,y,z,0)
        for (int p = tid; p < TILE; p += THREADS) {
            const int g = t0 + p;
            float x, y, z;
            if (dir == 0) {
                x = tgtb[g * 3 + 0];
                y = tgtb[g * 3 + 1];
                z = tgtb[g * 3 + 2];
            } else {
                x = srcb[g * 3 + 0] + flob[g * 3 + 0];
                y = srcb[g * 3 + 1] + flob[g * 3 + 1];
                z = srcb[g * 3 + 2] + flob[g * 3 + 2];
            }
            spts[p] = make_float4(x, y, z, 0.f);
        }
        __syncthreads();

#pragma unroll 8
        for (int j = 0; j < TILE; j++) {
            const float4 r = spts[j];
            const float dx = qx - r.x;
            const float dy = qy - r.y;
            const float dz = qz - r.z;
            const float d2 = fmaf(dx, dx, fmaf(dy, dy, dz * dz));
            const bool ins = d2 < best[0];
            // warp-uniform branch: skip insert machinery unless some lane inserts
            if (__any_sync(0xffffffffu, ins)) {
                // branch-free interior: non-inserting lanes' arrays are already
                // sorted, so the compare-exchange chain is a no-op for them.
                best[0] = ins ? d2 : best[0];
#pragma unroll
                for (int i = 0; i < KNN - 1; i++) {
                    const float a = best[i], c = best[i + 1];
                    best[i]     = fmaxf(a, c);
                    best[i + 1] = fminf(a, c);
                }
            }
        }
        __syncthreads();
    }

    // per-query sum of the 16 euclidean distances
    float s = 0.f;
#pragma unroll
    for (int i = 0; i < KNN; i++) s += sqrtf(best[i]);

    // deterministic block reduction
    __shared__ float warpsum[THREADS / 32];
#pragma unroll
    for (int o = 16; o > 0; o >>= 1) s += __shfl_down_sync(0xffffffffu, s, o);
    if ((tid & 31) == 0) warpsum[tid >> 5] = s;
    __syncthreads();
    if (tid == 0) {
        float tot = 0.f;
#pragma unroll
        for (int w = 0; w < THREADS / 32; w++) tot += warpsum[w];
        g_partials[blockIdx.x] = tot;
    }
}

__global__ void __launch_bounds__(NBLOCKS)
finalize_kernel(float* __restrict__ out) {
    __shared__ float sh[NBLOCKS];
    const int tid = threadIdx.x;
    sh[tid] = g_partials[tid];
    __syncthreads();
#pragma unroll
    for (int s = NBLOCKS / 2; s > 0; s >>= 1) {
        if (tid < s) sh[tid] += sh[tid + s];
        __syncthreads();
    }
    if (tid == 0) {
        out[0] = sh[0] * (1.0f / (float)(KNN * BATCH * NPTS));
    }
}

extern "C" void kernel_launch(void* const* d_in, const int* in_sizes, int n_in,
                              void* d_out, int out_size) {
    const float* src  = (const float*)d_in[0];   // pc_source [B, N, 3]
    const float* tgt  = (const float*)d_in[1];   // pc_target [B, M, 3]
    const float* flow = (const float*)d_in[2];   // pred_flow [B, N, 3]
    float* out = (float*)d_out;

    chamfer_knn_kernel<<<NBLOCKS, THREADS>>>(src, tgt, flow);
    finalize_kernel<<<1, NBLOCKS>>>(out);
}

// round 3
// speedup vs baseline: 1.3215x; 1.2745x over previous
#include <cuda_runtime.h>
#include <float.h>
#include <math.h>

#define BATCH 2
#define NPTS 8192
#define KNN 16
#define TILE 2048                       // 2048 * 16B = 32 KB static smem
#define THREADS 128
#define NBLOCKS (2 * BATCH * NPTS / THREADS)   // 256
#define NQ_TOTAL (2 * BATCH * NPTS)            // 32768 query slots
#define CAP 1024                        // candidate capacity per query
#define SUB 512                         // threshold-pass subset size

__device__ float g_partials[NBLOCKS];
// candidate scratch, column-major: slot i of query gq at g_scratch[i*NQ_TOTAL + gq]
__device__ float g_scratch[(size_t)CAP * NQ_TOTAL];   // 134 MB static

__global__ void __launch_bounds__(THREADS)
chamfer_knn_kernel(const float* __restrict__ src,
                   const float* __restrict__ tgt,
                   const float* __restrict__ flow) {
    __shared__ float4 spts[TILE];

    const int tid = threadIdx.x;
    const int gq  = blockIdx.x * THREADS + tid;       // global query slot
    const int blocks_per_set = NPTS / THREADS;        // 64
    const int set = blockIdx.x / blocks_per_set;      // (batch, direction)
    const int b   = set >> 1;
    const int dir = set & 1;                          // 0: pred->target, 1: target->pred
    const int qi  = (blockIdx.x % blocks_per_set) * THREADS + tid;

    const float* __restrict__ srcb = src  + (size_t)b * NPTS * 3;
    const float* __restrict__ tgtb = tgt  + (size_t)b * NPTS * 3;
    const float* __restrict__ flob = flow + (size_t)b * NPTS * 3;

    // query point
    float qx, qy, qz;
    if (dir == 0) {
        qx = srcb[qi * 3 + 0] + flob[qi * 3 + 0];
        qy = srcb[qi * 3 + 1] + flob[qi * 3 + 1];
        qz = srcb[qi * 3 + 2] + flob[qi * 3 + 2];
    } else {
        qx = tgtb[qi * 3 + 0];
        qy = tgtb[qi * 3 + 1];
        qz = tgtb[qi * 3 + 2];
    }
    const float q2 = qx * qx + qy * qy + qz * qz;

    // sorted-descending top-16 of score (best[0] = worst of the 16)
    float best[KNN];
#pragma unroll
    for (int i = 0; i < KNN; i++) best[i] = FLT_MAX;

    float tau = FLT_MAX;
    float* const wbase  = g_scratch + gq;
    float*       wp     = wbase;                                    // next write slot
    float* const wguard = wbase + (size_t)(CAP - 8) * NQ_TOTAL;     // unroll-8 slack

    for (int t0 = 0; t0 < NPTS; t0 += TILE) {
        // stage ref tile as (x, y, z, |r|^2/2)
        for (int p = tid; p < TILE; p += THREADS) {
            const int g = t0 + p;
            float x, y, z;
            if (dir == 0) {
                x = tgtb[g * 3 + 0];
                y = tgtb[g * 3 + 1];
                z = tgtb[g * 3 + 2];
            } else {
                x = srcb[g * 3 + 0] + flob[g * 3 + 0];
                y = srcb[g * 3 + 1] + flob[g * 3 + 1];
                z = srcb[g * 3 + 2] + flob[g * 3 + 2];
            }
            const float w = 0.5f * (x * x + (y * y + z * z));
            spts[p] = make_float4(x, y, z, w);
        }
        __syncthreads();

        if (t0 == 0) {
            // threshold pass: exact top-16 over the first SUB points
#pragma unroll 4
            for (int j = 0; j < SUB; j++) {
                const float4 r = spts[j];
                float sc = fmaf(-qx, r.x, r.w);
                sc = fmaf(-qy, r.y, sc);
                sc = fmaf(-qz, r.z, sc);
                const bool ins = sc < best[0];
                if (__any_sync(0xffffffffu, ins)) {
                    best[0] = ins ? sc : best[0];
#pragma unroll
                    for (int i = 0; i < KNN - 1; i++) {
                        const float a = best[i], c = best[i + 1];
                        best[i]     = fmaxf(a, c);
                        best[i + 1] = fminf(a, c);
                    }
                }
            }
            tau = best[0];  // upper bound on the true 16th-smallest score
        }

        // streaming collect: no top-k state, predicated store of candidates
        for (int j0 = 0; j0 < TILE; j0 += 8) {
            if (wp >= wguard) tau = -FLT_MAX;   // overflow belt (never fires statistically)
#pragma unroll
            for (int jj = 0; jj < 8; jj++) {
                const float4 r = spts[j0 + jj];
                float sc = fmaf(-qx, r.x, r.w);
                sc = fmaf(-qy, r.y, sc);
                sc = fmaf(-qz, r.z, sc);
                if (sc <= tau) {        // ~3% of lanes: predicated STG + ptr bump
                    *wp = sc;
                    wp += NQ_TOTAL;
                }
            }
        }
        __syncthreads();
    }

    // final exact selection over collected candidates (superset of true top-16)
    const int cnt = (int)((wp - wbase) / NQ_TOTAL);
    const int mcnt = __reduce_max_sync(0xffffffffu, cnt);
#pragma unroll
    for (int i = 0; i < KNN; i++) best[i] = FLT_MAX;   // reinit: avoid duplicates

    for (int i = 0; i < mcnt; i++) {
        const float v = wbase[(size_t)i * NQ_TOTAL];   // coalesced LDG
        const bool ins = (i < cnt) && (v < best[0]);
        if (__any_sync(0xffffffffu, ins)) {
            best[0] = ins ? v : best[0];
#pragma unroll
            for (int k = 0; k < KNN - 1; k++) {
                const float a = best[k], c = best[k + 1];
                best[k]     = fmaxf(a, c);
                best[k + 1] = fminf(a, c);
            }
        }
    }

    // per-query sum of the 16 euclidean distances: d = sqrt(2*score + |q|^2)
    float s = 0.f;
#pragma unroll
    for (int i = 0; i < KNN; i++) {
        const float d2 = fmaf(2.f, best[i], q2);
        s += sqrtf(fmaxf(d2, 0.f));
    }

    // deterministic block reduction
    __shared__ float warpsum[THREADS / 32];
#pragma unroll
    for (int o = 16; o > 0; o >>= 1) s += __shfl_down_sync(0xffffffffu, s, o);
    if ((tid & 31) == 0) warpsum[tid >> 5] = s;
    __syncthreads();
    if (tid == 0) {
        float tot = 0.f;
#pragma unroll
        for (int w = 0; w < THREADS / 32; w++) tot += warpsum[w];
        g_partials[blockIdx.x] = tot;
    }
}

__global__ void __launch_bounds__(NBLOCKS)
finalize_kernel(float* __restrict__ out) {
    __shared__ float sh[NBLOCKS];
    const int tid = threadIdx.x;
    sh[tid] = g_partials[tid];
    __syncthreads();
#pragma unroll
    for (int s = NBLOCKS / 2; s > 0; s >>= 1) {
        if (tid < s) sh[tid] += sh[tid + s];
        __syncthreads();
    }
    if (tid == 0) {
        out[0] = sh[0] * (1.0f / (float)(KNN * BATCH * NPTS));
    }
}

extern "C" void kernel_launch(void* const* d_in, const int* in_sizes, int n_in,
                              void* d_out, int out_size) {
    const float* src  = (const float*)d_in[0];   // pc_source [B, N, 3]
    const float* tgt  = (const float*)d_in[1];   // pc_target [B, M, 3]
    const float* flow = (const float*)d_in[2];   // pred_flow [B, N, 3]
    float* out = (float*)d_out;

    chamfer_knn_kernel<<<NBLOCKS, THREADS>>>(src, tgt, flow);
    finalize_kernel<<<1, NBLOCKS>>>(out);
}